// round 15
// baseline (speedup 1.0000x reference)
#include <cuda_runtime.h>
#include <cstdint>

using ull = unsigned long long;

// ---- folded weights in one constant struct ----
struct ConstW {
    ull pG[72];    // [e][p] = (G[e][2p], G[e][2p+1]),  G = Wq^T Wk
    ull pWvo[72];  // [e][p] = (Wvo[2p][e], Wvo[2p+1][e]),  Wvo = Wo @ Wv
    ull pW1[144];  // [e][p] p<12
    ull pW2[144];  // [f][p] p<6
    ull pa[6];     // a[e]  = sum_d Wq[d][e] * bk[d]   (pairs)
    ull pbd[6];    // b[f]  = sum_d bq[d] * Wk[d][f]   (pairs)
    ull pbvo[6];   // bvo   = Wo @ bv                  (pairs)
    ull pbo[6], pb1[12], pb2[6];
    float cS;      // bq . bk
};

__constant__ ConstW cw;

namespace {

constexpr int N = 8;
constexpr int D = 12;
constexpr int F = 24;
constexpr int V = 128;
constexpr int WARPS = 8;
constexpr int THREADS = WARPS * 32;
constexpr int ITEMS_PER_BLOCK = 32;   // 4 items per warp
constexpr int XROW = 16;              // X row stride (12 data + d at [12])
constexpr int ISTX = 132;             // X item stride (bank stagger +4/group)
constexpr int XV   = 4 * ISTX;        // V' region offset (528)
constexpr int ISTV = 100;             // V' item stride (bank stagger +4/group)
constexpr int SCR  = XV + 4 * ISTV;   // 928 floats per warp

#define F4C(p) (*reinterpret_cast<const float4*>(p))
#define F4(p)  (*reinterpret_cast<float4*>(p))

__device__ __forceinline__ ull pack2(float x, float y) {
    ull p; asm("mov.b64 %0, {%1, %2};" : "=l"(p) : "f"(x), "f"(y)); return p;
}
__device__ __forceinline__ void unpack2(ull p, float& x, float& y) {
    asm("mov.b64 {%0, %1}, %2;" : "=f"(x), "=f"(y) : "l"(p));
}
__device__ __forceinline__ void ffma2(ull& d, ull a, ull b) {
    asm("fma.rn.f32x2 %0, %1, %2, %0;" : "+l"(d) : "l"(a), "l"(b));
}

// ---- pack kernel: fold weights, pair-pack, write into constant bank ----
__global__ void pack_weights_kernel(
    ConstW* __restrict__ dst,
    const float* __restrict__ Wq, const float* __restrict__ bq,
    const float* __restrict__ Wk, const float* __restrict__ bk,
    const float* __restrict__ Wv, const float* __restrict__ bv,
    const float* __restrict__ Wo, const float* __restrict__ bo,
    const float* __restrict__ W1, const float* __restrict__ b1,
    const float* __restrict__ W2, const float* __restrict__ b2)
{
    const int t = threadIdx.x;
    // G = Wq^T Wk : pG[e*6+p] = (G[e][2p], G[e][2p+1])
    for (int i = t; i < 72; i += 256) {
        int e = i / 6, p = i % 6;
        float g0 = 0.f, g1 = 0.f;
        for (int d = 0; d < D; d++) {
            g0 += Wq[d * D + e] * Wk[d * D + 2*p];
            g1 += Wq[d * D + e] * Wk[d * D + 2*p + 1];
        }
        dst->pG[i] = pack2(g0, g1);
    }
    // Wvo = Wo @ Wv : pWvo[e*6+p] = (Wvo[2p][e], Wvo[2p+1][e])
    for (int i = t; i < 72; i += 256) {
        int e = i / 6, p = i % 6;
        float w0 = 0.f, w1 = 0.f;
        for (int d = 0; d < D; d++) {
            w0 += Wo[(2*p)     * D + d] * Wv[d * D + e];
            w1 += Wo[(2*p + 1) * D + d] * Wv[d * D + e];
        }
        dst->pWvo[i] = pack2(w0, w1);
    }
    for (int i = t; i < 144; i += 256) {
        int e = i / 12, p = i % 12;
        dst->pW1[i] = pack2(W1[(2*p) * D + e], W1[(2*p+1) * D + e]);
    }
    for (int i = t; i < 144; i += 256) {
        int f = i / 6, p = i % 6;
        dst->pW2[i] = pack2(W2[(2*p) * F + f], W2[(2*p+1) * F + f]);
    }
    if (t < 6) {
        float a0 = 0.f, a1 = 0.f, b0 = 0.f, b1v = 0.f, v0 = 0.f, v1 = 0.f;
        for (int d = 0; d < D; d++) {
            a0  += Wq[d * D + 2*t]     * bk[d];
            a1  += Wq[d * D + 2*t + 1] * bk[d];
            b0  += bq[d] * Wk[d * D + 2*t];
            b1v += bq[d] * Wk[d * D + 2*t + 1];
            v0  += Wo[(2*t)     * D + d] * bv[d];
            v1  += Wo[(2*t + 1) * D + d] * bv[d];
        }
        dst->pa[t]   = pack2(a0, a1);
        dst->pbd[t]  = pack2(b0, b1v);
        dst->pbvo[t] = pack2(v0, v1);
        dst->pbo[t]  = pack2(bo[2*t], bo[2*t+1]);
        dst->pb2[t]  = pack2(b2[2*t], b2[2*t+1]);
    }
    if (t < 12) dst->pb1[t] = pack2(b1[2*t], b1[2*t+1]);
    if (t == 0) {
        float c = 0.f;
        for (int d = 0; d < D; d++) c += bq[d] * bk[d];
        dst->cS = c;
    }
}

__global__ __launch_bounds__(THREADS, 3)
void tiny_transformer_kernel(
    const int*   __restrict__ x,
    const float* __restrict__ embed,
    const float* __restrict__ pos,
    const float* __restrict__ blm,
    float* __restrict__ out)
{
    // ---- shared ----
    __shared__ __align__(16) float sEmbT[D * V];   // transposed [d][v] for logits
    __shared__ __align__(16) float sPos[N * D];
    __shared__ __align__(16) float sBlm[V];
    // per-warp scratch: X rows (+d) at [0..528), V' rows at [528..928);
    // low 384 floats reused for final X in phase 9.
    __shared__ __align__(16) float sScr[WARPS][SCR];

    const int tid = threadIdx.x;

    for (int i = tid; i < D * V; i += THREADS) {
        int d = i >> 7, v = i & 127;
        sEmbT[i] = embed[v * D + d];
    }
    for (int i = tid; i < N * D; i += THREADS) sPos[i] = pos[i];
    for (int i = tid; i < V; i += THREADS) sBlm[i] = blm[i];
    __syncthreads();

    const int w    = tid >> 5;
    const int lane = tid & 31;
    const int n    = lane & 7;            // token within item
    const int g    = lane >> 3;           // item within warp
    const int item_base = blockIdx.x * ITEMS_PER_BLOCK + w * 4;

    // ---- phase 1: X = embed[x] + pos ----
    const int tok = __ldg(&x[item_base * N + lane]);
    float X[D];
    {
        const float4* e4 = reinterpret_cast<const float4*>(embed);
        #pragma unroll
        for (int c = 0; c < 3; c++) {
            float4 e = __ldg(&e4[tok * 3 + c]);
            float4 p = F4C(&sPos[n * D + 4 * c]);
            X[4*c+0] = e.x + p.x; X[4*c+1] = e.y + p.y;
            X[4*c+2] = e.z + p.z; X[4*c+3] = e.w + p.w;
        }
    }

    // ---- phase 2: Y = X@G, V' = X@Wvo^T + bvo, bias dots; X,V' -> smem ----
    ull y2[6];
    float cOwn;
    {
        ull v2[6];
        #pragma unroll
        for (int p = 0; p < 6; p++) { y2[p] = 0; v2[p] = cw.pbvo[p]; }
        #pragma unroll
        for (int e = 0; e < D; e++) {
            const ull xp = pack2(X[e], X[e]);
            #pragma unroll
            for (int p = 0; p < 6; p++) {
                ffma2(y2[p], xp, cw.pG[e * 6 + p]);
                ffma2(v2[p], xp, cw.pWvo[e * 6 + p]);
            }
        }
        // bias dots: cOwn = X.a ; dOwn = X.b
        ull cacc = 0, dacc = 0;
        #pragma unroll
        for (int p = 0; p < 6; p++) {
            const ull xq = pack2(X[2*p], X[2*p+1]);
            ffma2(cacc, xq, cw.pa[p]);
            ffma2(dacc, xq, cw.pbd[p]);
        }
        float cu, cv, du, dv;
        unpack2(cacc, cu, cv); cOwn = cu + cv;
        unpack2(dacc, du, dv); const float dOwn = du + dv;

        // store X row (+d) for score phase
        float* xr = &sScr[w][g * ISTX + n * XROW];
        F4(xr)     = make_float4(X[0], X[1], X[2],  X[3]);
        F4(xr + 4) = make_float4(X[4], X[5], X[6],  X[7]);
        F4(xr + 8) = make_float4(X[8], X[9], X[10], X[11]);
        xr[12] = dOwn;
        // store V' row packed-natural
        ulonglong2* vd =
            reinterpret_cast<ulonglong2*>(&sScr[w][XV + g * ISTV + n * D]);
        vd[0] = make_ulonglong2(v2[0], v2[1]);
        vd[1] = make_ulonglong2(v2[2], v2[3]);
        vd[2] = make_ulonglong2(v2[4], v2[5]);
    }
    __syncwarp();

    // ---- phase 3: S[n][m] = (Y_n.X_m + c_n + d_m + cS)/sqrt(D) ----
    float S[N];
    {
        const float inv_scale = 0.28867513459481287f;  // 1/sqrt(12)
        const float* xb = &sScr[w][g * ISTX];
        const float base = cOwn + cw.cS;
        #pragma unroll
        for (int m = 0; m < N; m++) {
            const ulonglong2* xm =
                reinterpret_cast<const ulonglong2*>(xb + m * XROW);
            ulonglong2 r0 = xm[0], r1 = xm[1], r2 = xm[2];
            ull acc = 0;
            ffma2(acc, y2[0], r0.x); ffma2(acc, y2[1], r0.y);
            ffma2(acc, y2[2], r1.x); ffma2(acc, y2[3], r1.y);
            ffma2(acc, y2[4], r2.x); ffma2(acc, y2[5], r2.y);
            float u, v; unpack2(acc, u, v);
            const float dm = xb[m * XROW + 12];
            S[m] = (m <= n) ? (u + v + base + dm) * inv_scale : -1e30f;
        }
    }

    // ---- phase 4: softmax ----
    {
        float mx = S[0];
        #pragma unroll
        for (int m = 1; m < N; m++) mx = fmaxf(mx, S[m]);
        float sum = 0.f;
        #pragma unroll
        for (int m = 0; m < N; m++) { S[m] = __expf(S[m] - mx); sum += S[m]; }
        const float inv = 1.f / sum;
        #pragma unroll
        for (int m = 0; m < N; m++) S[m] *= inv;
    }

    // ---- phase 5+6: X += softmax @ V' + bo  (VO-folded attention out) ----
    {
        ull a2[6] = {0, 0, 0, 0, 0, 0};
        const ulonglong2* vb =
            reinterpret_cast<const ulonglong2*>(&sScr[w][XV + g * ISTV]);
        #pragma unroll
        for (int m = 0; m < N; m++) {
            const ull sp = pack2(S[m], S[m]);
            ulonglong2 r0 = vb[m * 3], r1 = vb[m * 3 + 1], r2 = vb[m * 3 + 2];
            ffma2(a2[0], sp, r0.x); ffma2(a2[1], sp, r0.y);
            ffma2(a2[2], sp, r1.x); ffma2(a2[3], sp, r1.y);
            ffma2(a2[4], sp, r2.x); ffma2(a2[5], sp, r2.y);
        }
        #pragma unroll
        for (int p = 0; p < 6; p++) {
            float u, v, bu, bv_;
            unpack2(a2[p], u, v);
            unpack2(cw.pbo[p], bu, bv_);
            X[2*p]   += u + bu;
            X[2*p+1] += v + bv_;
        }
    }

    // ---- phase 7: H = relu(X @ W1^T + b1) (packed) ----
    float H[F];
    {
        ull h2[12];
        #pragma unroll
        for (int p = 0; p < 12; p++) h2[p] = cw.pb1[p];
        #pragma unroll
        for (int e = 0; e < D; e++) {
            const ull xp = pack2(X[e], X[e]);
            #pragma unroll
            for (int p = 0; p < 12; p++)
                ffma2(h2[p], xp, cw.pW1[e * 12 + p]);
        }
        #pragma unroll
        for (int p = 0; p < 12; p++) {
            float u, v; unpack2(h2[p], u, v);
            H[2*p]   = fmaxf(u, 0.f);
            H[2*p+1] = fmaxf(v, 0.f);
        }
    }

    // ---- phase 8: X += H @ W2^T + b2 (packed) ----
    {
        ull x2[6];
        #pragma unroll
        for (int p = 0; p < 6; p++) x2[p] = cw.pb2[p];
        #pragma unroll
        for (int f = 0; f < F; f++) {
            const ull hp = pack2(H[f], H[f]);
            #pragma unroll
            for (int p = 0; p < 6; p++)
                ffma2(x2[p], hp, cw.pW2[f * 6 + p]);
        }
        #pragma unroll
        for (int p = 0; p < 6; p++) {
            float u, v; unpack2(x2[p], u, v);
            X[2*p] += u; X[2*p+1] += v;
        }
    }

    // ---- hand off final X (reuses scratch; all reads done) ----
    __syncwarp();
    {
        float* dst = &sScr[w][lane * D];
        F4(dst)     = make_float4(X[0], X[1], X[2],  X[3]);
        F4(dst + 4) = make_float4(X[4], X[5], X[6],  X[7]);
        F4(dst + 8) = make_float4(X[8], X[9], X[10], X[11]);
    }
    __syncwarp();

    // ---- phase 9: logits = Xf @ embed^T + b_lm (single pass, 4 cols/lane) ----
    {
        const int v0 = lane * 4;
        ull e01[D], e23[D];
        #pragma unroll
        for (int d = 0; d < D; d++) {
            float4 e = F4C(&sEmbT[d * V + v0]);
            e01[d] = pack2(e.x, e.y);
            e23[d] = pack2(e.z, e.w);
        }
        const float4 bl = F4C(&sBlm[v0]);
        const ull bl01 = pack2(bl.x, bl.y);
        const ull bl23 = pack2(bl.z, bl.w);

        float* obase = out + (size_t)item_base * (N * V) + v0;
        const float* xf = sScr[w];

        for (int r = 0; r < 4 * N; r++) {
            float4 xa = F4C(&xf[r * D]);       // broadcast reads
            float4 xb = F4C(&xf[r * D + 4]);
            float4 xc = F4C(&xf[r * D + 8]);
            const float xr[D] = {xa.x, xa.y, xa.z, xa.w,
                                 xb.x, xb.y, xb.z, xb.w,
                                 xc.x, xc.y, xc.z, xc.w};
            ull a01 = bl01, a23 = bl23;
            #pragma unroll
            for (int d = 0; d < D; d++) {
                const ull xv2 = pack2(xr[d], xr[d]);
                ffma2(a01, xv2, e01[d]);
                ffma2(a23, xv2, e23[d]);
            }
            float4 acc;
            unpack2(a01, acc.x, acc.y);
            unpack2(a23, acc.z, acc.w);
            F4(&obase[(size_t)r * V]) = acc;   // coalesced 512B per warp-row
        }
    }
}

}  // namespace

extern "C" void kernel_launch(void* const* d_in, const int* in_sizes, int n_in,
                              void* d_out, int out_size)
{
    const int*   x     = (const int*)  d_in[0];
    const float* embed = (const float*)d_in[1];
    const float* pos   = (const float*)d_in[2];
    const float* blm   = (const float*)d_in[15];
    float* out = (float*)d_out;

    // symbol address query (host-side, not a captured op)
    void* cwAddr = nullptr;
    cudaGetSymbolAddress(&cwAddr, cw);

    // 1) fold + pair-pack all weights DIRECTLY into the constant bank
    pack_weights_kernel<<<1, 256>>>(
        (ConstW*)cwAddr,
        (const float*)d_in[3],  (const float*)d_in[4],
        (const float*)d_in[5],  (const float*)d_in[6],
        (const float*)d_in[7],  (const float*)d_in[8],
        (const float*)d_in[9],  (const float*)d_in[10],
        (const float*)d_in[11], (const float*)d_in[12],
        (const float*)d_in[13], (const float*)d_in[14]);

    // 2) main kernel
    const int batch  = in_sizes[0] / N;              // 32768
    const int blocks = batch / ITEMS_PER_BLOCK;      // 1024

    tiny_transformer_kernel<<<blocks, THREADS>>>(x, embed, pos, blm, out);
}

// round 16
// speedup vs baseline: 1.0594x; 1.0594x over previous
#include <cuda_runtime.h>
#include <cstdint>

using ull = unsigned long long;

// ---- folded weights in one constant struct ----
struct ConstW {
    ull pG[72];    // [e][p] = (G[e][2p], G[e][2p+1]),  G = Wq^T Wk
    ull pWvo[72];  // [e][p] = (Wvo[2p][e], Wvo[2p+1][e]),  Wvo = Wo @ Wv
    ull pW1[144];  // [e][p] p<12
    ull pW2[144];  // [f][p] p<6
    ull pa[6];     // a[e]  = sum_d Wq[d][e] * bk[d]   (pairs)
    ull pbd[6];    // b[f]  = sum_d bq[d] * Wk[d][f]   (pairs)
    ull pbvo[6];   // bvo   = Wo @ bv                  (pairs)
    ull pbo[6], pb1[12], pb2[6];
    float cS;      // bq . bk
};

__constant__ ConstW cw;

namespace {

constexpr int N = 8;
constexpr int D = 12;
constexpr int F = 24;
constexpr int V = 128;
constexpr int WARPS = 8;
constexpr int THREADS = WARPS * 32;
constexpr int ITEMS_PER_BLOCK = 32;   // 4 items per warp
constexpr int XROW = 16;              // X row stride (12 data + d at [12])
constexpr int ISTX = 132;             // X item stride (bank stagger +4/group)
constexpr int XV   = 4 * ISTX;        // V' region offset (528)
constexpr int ISTV = 100;             // V' item stride (bank stagger +4/group)
constexpr int SCR  = XV + 4 * ISTV;   // 928 floats per warp

#define F4C(p) (*reinterpret_cast<const float4*>(p))
#define F4(p)  (*reinterpret_cast<float4*>(p))

__device__ __forceinline__ ull pack2(float x, float y) {
    ull p; asm("mov.b64 %0, {%1, %2};" : "=l"(p) : "f"(x), "f"(y)); return p;
}
__device__ __forceinline__ void unpack2(ull p, float& x, float& y) {
    asm("mov.b64 {%0, %1}, %2;" : "=f"(x), "=f"(y) : "l"(p));
}
__device__ __forceinline__ void ffma2(ull& d, ull a, ull b) {
    asm("fma.rn.f32x2 %0, %1, %2, %0;" : "+l"(d) : "l"(a), "l"(b));
}

// ---- pack kernel: stage weights to smem (coalesced), fold from smem,
//      write pair-packed results into the constant bank ----
__global__ void pack_weights_kernel(
    ConstW* __restrict__ dst,
    const float* __restrict__ Wq, const float* __restrict__ bq,
    const float* __restrict__ Wk, const float* __restrict__ bk,
    const float* __restrict__ Wv, const float* __restrict__ bv,
    const float* __restrict__ Wo, const float* __restrict__ bo,
    const float* __restrict__ W1, const float* __restrict__ b1,
    const float* __restrict__ W2, const float* __restrict__ b2)
{
    __shared__ float sWq[144], sWk[144], sWv[144], sWo[144];
    __shared__ float sW1[288], sW2[288];
    __shared__ float sbq[12], sbk[12], sbv[12], sbo[12], sb2[12], sb1[24];

    const int t = threadIdx.x;

    // coalesced parallel staging (independent loads, latency overlapped)
    if (t < 144) { sWq[t] = Wq[t]; sWk[t] = Wk[t]; sWv[t] = Wv[t]; sWo[t] = Wo[t]; }
    {
        int u = t - 144;
        if (u >= 0 && u < 112) {           // 144..255 covers first 112 of W1/W2
            sW1[u] = W1[u]; sW2[u] = W2[u];
        }
    }
    if (t < 176) { sW1[112 + t] = W1[112 + t]; sW2[112 + t] = W2[112 + t]; }
    if (t < 12) {
        sbq[t] = bq[t]; sbk[t] = bk[t]; sbv[t] = bv[t];
        sbo[t] = bo[t]; sb2[t] = b2[t];
    }
    if (t < 24) sb1[t] = b1[t];
    __syncthreads();

    // G = Wq^T Wk : pG[e*6+p] = (G[e][2p], G[e][2p+1])
    if (t < 72) {
        int e = t / 6, p = t % 6;
        float g0 = 0.f, g1 = 0.f;
        #pragma unroll
        for (int d = 0; d < D; d++) {
            g0 += sWq[d * D + e] * sWk[d * D + 2*p];
            g1 += sWq[d * D + e] * sWk[d * D + 2*p + 1];
        }
        dst->pG[t] = pack2(g0, g1);
    }
    // Wvo = Wo @ Wv : pWvo[e*6+p] = (Wvo[2p][e], Wvo[2p+1][e])
    if (t >= 72 && t < 144) {
        int i = t - 72;
        int e = i / 6, p = i % 6;
        float w0 = 0.f, w1 = 0.f;
        #pragma unroll
        for (int d = 0; d < D; d++) {
            w0 += sWo[(2*p)     * D + d] * sWv[d * D + e];
            w1 += sWo[(2*p + 1) * D + d] * sWv[d * D + e];
        }
        dst->pWvo[i] = pack2(w0, w1);
    }
    for (int i = t; i < 144; i += 256) {
        int e = i / 12, p = i % 12;
        dst->pW1[i] = pack2(sW1[(2*p) * D + e], sW1[(2*p+1) * D + e]);
    }
    for (int i = t; i < 144; i += 256) {
        int f = i / 6, p = i % 6;
        dst->pW2[i] = pack2(sW2[(2*p) * F + f], sW2[(2*p+1) * F + f]);
    }
    if (t >= 144 && t < 150) {
        int q = t - 144;
        float a0 = 0.f, a1 = 0.f, b0 = 0.f, b1v = 0.f, v0 = 0.f, v1 = 0.f;
        #pragma unroll
        for (int d = 0; d < D; d++) {
            a0  += sWq[d * D + 2*q]     * sbk[d];
            a1  += sWq[d * D + 2*q + 1] * sbk[d];
            b0  += sbq[d] * sWk[d * D + 2*q];
            b1v += sbq[d] * sWk[d * D + 2*q + 1];
            v0  += sWo[(2*q)     * D + d] * sbv[d];
            v1  += sWo[(2*q + 1) * D + d] * sbv[d];
        }
        dst->pa[q]   = pack2(a0, a1);
        dst->pbd[q]  = pack2(b0, b1v);
        dst->pbvo[q] = pack2(v0, v1);
        dst->pbo[q]  = pack2(sbo[2*q], sbo[2*q+1]);
        dst->pb2[q]  = pack2(sb2[2*q], sb2[2*q+1]);
    }
    if (t >= 150 && t < 162) {
        int q = t - 150;
        dst->pb1[q] = pack2(sb1[2*q], sb1[2*q+1]);
    }
    if (t == 162) {
        float c = 0.f;
        #pragma unroll
        for (int d = 0; d < D; d++) c += sbq[d] * sbk[d];
        dst->cS = c;
    }
}

__global__ __launch_bounds__(THREADS, 3)
void tiny_transformer_kernel(
    const int*   __restrict__ x,
    const float* __restrict__ embed,
    const float* __restrict__ pos,
    const float* __restrict__ blm,
    float* __restrict__ out)
{
    // ---- shared ----
    __shared__ __align__(16) float sEmbT[D * V];   // transposed [d][v] for logits
    __shared__ __align__(16) float sPos[N * D];
    __shared__ __align__(16) float sBlm[V];
    // per-warp scratch: X rows (+d) at [0..528), V' rows at [528..928);
    // low 384 floats reused for final X in phase 9.
    __shared__ __align__(16) float sScr[WARPS][SCR];

    const int tid = threadIdx.x;

    for (int i = tid; i < D * V; i += THREADS) {
        int d = i >> 7, v = i & 127;
        sEmbT[i] = embed[v * D + d];
    }
    for (int i = tid; i < N * D; i += THREADS) sPos[i] = pos[i];
    for (int i = tid; i < V; i += THREADS) sBlm[i] = blm[i];
    __syncthreads();

    const int w    = tid >> 5;
    const int lane = tid & 31;
    const int n    = lane & 7;            // token within item
    const int g    = lane >> 3;           // item within warp
    const int item_base = blockIdx.x * ITEMS_PER_BLOCK + w * 4;

    // ---- phase 1: X = embed[x] + pos ----
    const int tok = __ldg(&x[item_base * N + lane]);
    float X[D];
    {
        const float4* e4 = reinterpret_cast<const float4*>(embed);
        #pragma unroll
        for (int c = 0; c < 3; c++) {
            float4 e = __ldg(&e4[tok * 3 + c]);
            float4 p = F4C(&sPos[n * D + 4 * c]);
            X[4*c+0] = e.x + p.x; X[4*c+1] = e.y + p.y;
            X[4*c+2] = e.z + p.z; X[4*c+3] = e.w + p.w;
        }
    }

    // ---- phase 2: Y = X@G, V' = X@Wvo^T + bvo, bias dots; X,V' -> smem ----
    ull y2[6];
    float cOwn;
    {
        ull v2[6];
        #pragma unroll
        for (int p = 0; p < 6; p++) { y2[p] = 0; v2[p] = cw.pbvo[p]; }
        #pragma unroll
        for (int e = 0; e < D; e++) {
            const ull xp = pack2(X[e], X[e]);
            #pragma unroll
            for (int p = 0; p < 6; p++) {
                ffma2(y2[p], xp, cw.pG[e * 6 + p]);
                ffma2(v2[p], xp, cw.pWvo[e * 6 + p]);
            }
        }
        // bias dots: cOwn = X.a ; dOwn = X.b
        ull cacc = 0, dacc = 0;
        #pragma unroll
        for (int p = 0; p < 6; p++) {
            const ull xq = pack2(X[2*p], X[2*p+1]);
            ffma2(cacc, xq, cw.pa[p]);
            ffma2(dacc, xq, cw.pbd[p]);
        }
        float cu, cv, du, dv;
        unpack2(cacc, cu, cv); cOwn = cu + cv;
        unpack2(dacc, du, dv); const float dOwn = du + dv;

        // store X row (+d) for score phase
        float* xr = &sScr[w][g * ISTX + n * XROW];
        F4(xr)     = make_float4(X[0], X[1], X[2],  X[3]);
        F4(xr + 4) = make_float4(X[4], X[5], X[6],  X[7]);
        F4(xr + 8) = make_float4(X[8], X[9], X[10], X[11]);
        xr[12] = dOwn;
        // store V' row packed-natural
        ulonglong2* vd =
            reinterpret_cast<ulonglong2*>(&sScr[w][XV + g * ISTV + n * D]);
        vd[0] = make_ulonglong2(v2[0], v2[1]);
        vd[1] = make_ulonglong2(v2[2], v2[3]);
        vd[2] = make_ulonglong2(v2[4], v2[5]);
    }
    __syncwarp();

    // ---- phase 3: S[n][m] = (Y_n.X_m + c_n + d_m + cS)/sqrt(D) ----
    float S[N];
    {
        const float inv_scale = 0.28867513459481287f;  // 1/sqrt(12)
        const float* xb = &sScr[w][g * ISTX];
        const float base = cOwn + cw.cS;
        #pragma unroll
        for (int m = 0; m < N; m++) {
            const ulonglong2* xm =
                reinterpret_cast<const ulonglong2*>(xb + m * XROW);
            ulonglong2 r0 = xm[0], r1 = xm[1], r2 = xm[2];
            ull acc = 0;
            ffma2(acc, y2[0], r0.x); ffma2(acc, y2[1], r0.y);
            ffma2(acc, y2[2], r1.x); ffma2(acc, y2[3], r1.y);
            ffma2(acc, y2[4], r2.x); ffma2(acc, y2[5], r2.y);
            float u, v; unpack2(acc, u, v);
            const float dm = xb[m * XROW + 12];
            S[m] = (m <= n) ? (u + v + base + dm) * inv_scale : -1e30f;
        }
    }

    // ---- phase 4: softmax ----
    {
        float mx = S[0];
        #pragma unroll
        for (int m = 1; m < N; m++) mx = fmaxf(mx, S[m]);
        float sum = 0.f;
        #pragma unroll
        for (int m = 0; m < N; m++) { S[m] = __expf(S[m] - mx); sum += S[m]; }
        const float inv = 1.f / sum;
        #pragma unroll
        for (int m = 0; m < N; m++) S[m] *= inv;
    }

    // ---- phase 5+6: X += softmax @ V' + bo  (VO-folded attention out) ----
    {
        ull a2[6] = {0, 0, 0, 0, 0, 0};
        const ulonglong2* vb =
            reinterpret_cast<const ulonglong2*>(&sScr[w][XV + g * ISTV]);
        #pragma unroll
        for (int m = 0; m < N; m++) {
            const ull sp = pack2(S[m], S[m]);
            ulonglong2 r0 = vb[m * 3], r1 = vb[m * 3 + 1], r2 = vb[m * 3 + 2];
            ffma2(a2[0], sp, r0.x); ffma2(a2[1], sp, r0.y);
            ffma2(a2[2], sp, r1.x); ffma2(a2[3], sp, r1.y);
            ffma2(a2[4], sp, r2.x); ffma2(a2[5], sp, r2.y);
        }
        #pragma unroll
        for (int p = 0; p < 6; p++) {
            float u, v, bu, bv_;
            unpack2(a2[p], u, v);
            unpack2(cw.pbo[p], bu, bv_);
            X[2*p]   += u + bu;
            X[2*p+1] += v + bv_;
        }
    }

    // ---- phase 7: H = relu(X @ W1^T + b1) (packed) ----
    float H[F];
    {
        ull h2[12];
        #pragma unroll
        for (int p = 0; p < 12; p++) h2[p] = cw.pb1[p];
        #pragma unroll
        for (int e = 0; e < D; e++) {
            const ull xp = pack2(X[e], X[e]);
            #pragma unroll
            for (int p = 0; p < 12; p++)
                ffma2(h2[p], xp, cw.pW1[e * 12 + p]);
        }
        #pragma unroll
        for (int p = 0; p < 12; p++) {
            float u, v; unpack2(h2[p], u, v);
            H[2*p]   = fmaxf(u, 0.f);
            H[2*p+1] = fmaxf(v, 0.f);
        }
    }

    // ---- phase 8: X += H @ W2^T + b2 (packed) ----
    {
        ull x2[6];
        #pragma unroll
        for (int p = 0; p < 6; p++) x2[p] = cw.pb2[p];
        #pragma unroll
        for (int f = 0; f < F; f++) {
            const ull hp = pack2(H[f], H[f]);
            #pragma unroll
            for (int p = 0; p < 6; p++)
                ffma2(x2[p], hp, cw.pW2[f * 6 + p]);
        }
        #pragma unroll
        for (int p = 0; p < 6; p++) {
            float u, v; unpack2(x2[p], u, v);
            X[2*p] += u; X[2*p+1] += v;
        }
    }

    // ---- hand off final X (reuses scratch; all reads done) ----
    __syncwarp();
    {
        float* dst = &sScr[w][lane * D];
        F4(dst)     = make_float4(X[0], X[1], X[2],  X[3]);
        F4(dst + 4) = make_float4(X[4], X[5], X[6],  X[7]);
        F4(dst + 8) = make_float4(X[8], X[9], X[10], X[11]);
    }
    __syncwarp();

    // ---- phase 9: logits = Xf @ embed^T + b_lm (single pass, 4 cols/lane) ----
    {
        const int v0 = lane * 4;
        ull e01[D], e23[D];
        #pragma unroll
        for (int d = 0; d < D; d++) {
            float4 e = F4C(&sEmbT[d * V + v0]);
            e01[d] = pack2(e.x, e.y);
            e23[d] = pack2(e.z, e.w);
        }
        const float4 bl = F4C(&sBlm[v0]);
        const ull bl01 = pack2(bl.x, bl.y);
        const ull bl23 = pack2(bl.z, bl.w);

        float* obase = out + (size_t)item_base * (N * V) + v0;
        const float* xf = sScr[w];

        for (int r = 0; r < 4 * N; r++) {
            float4 xa = F4C(&xf[r * D]);       // broadcast reads
            float4 xb = F4C(&xf[r * D + 4]);
            float4 xc = F4C(&xf[r * D + 8]);
            const float xr[D] = {xa.x, xa.y, xa.z, xa.w,
                                 xb.x, xb.y, xb.z, xb.w,
                                 xc.x, xc.y, xc.z, xc.w};
            ull a01 = bl01, a23 = bl23;
            #pragma unroll
            for (int d = 0; d < D; d++) {
                const ull xv2 = pack2(xr[d], xr[d]);
                ffma2(a01, xv2, e01[d]);
                ffma2(a23, xv2, e23[d]);
            }
            float4 acc;
            unpack2(a01, acc.x, acc.y);
            unpack2(a23, acc.z, acc.w);
            F4(&obase[(size_t)r * V]) = acc;   // coalesced 512B per warp-row
        }
    }
}

}  // namespace

extern "C" void kernel_launch(void* const* d_in, const int* in_sizes, int n_in,
                              void* d_out, int out_size)
{
    const int*   x     = (const int*)  d_in[0];
    const float* embed = (const float*)d_in[1];
    const float* pos   = (const float*)d_in[2];
    const float* blm   = (const float*)d_in[15];
    float* out = (float*)d_out;

    // symbol address query (host-side, not a captured op)
    void* cwAddr = nullptr;
    cudaGetSymbolAddress(&cwAddr, cw);

    // 1) fold + pair-pack all weights DIRECTLY into the constant bank
    pack_weights_kernel<<<1, 256>>>(
        (ConstW*)cwAddr,
        (const float*)d_in[3],  (const float*)d_in[4],
        (const float*)d_in[5],  (const float*)d_in[6],
        (const float*)d_in[7],  (const float*)d_in[8],
        (const float*)d_in[9],  (const float*)d_in[10],
        (const float*)d_in[11], (const float*)d_in[12],
        (const float*)d_in[13], (const float*)d_in[14]);

    // 2) main kernel
    const int batch  = in_sizes[0] / N;              // 32768
    const int blocks = batch / ITEMS_PER_BLOCK;      // 1024

    tiny_transformer_kernel<<<blocks, THREADS>>>(x, embed, pos, blm, out);
}

// round 17
// speedup vs baseline: 1.1142x; 1.0518x over previous
#include <cuda_runtime.h>
#include <cstdint>

using ull = unsigned long long;

// ---- folded weights in one constant struct ----
struct ConstW {
    ull pG[72];    // [e][p] = (G[e][2p], G[e][2p+1]),  G = Wq^T Wk
    ull pWvo[72];  // [e][p] = (Wvo[2p][e], Wvo[2p+1][e]),  Wvo = Wo @ Wv
    ull pW1[144];  // [e][p] p<12
    ull pW2[144];  // [f][p] p<6
    ull pa[6];     // a[e]  = sum_d Wq[d][e] * bk[d]   (pairs)
    ull pbd[6];    // b[f]  = sum_d bq[d] * Wk[d][f]   (pairs)
    ull pbvo[6];   // bvo   = Wo @ bv                  (pairs)
    ull pbo[6], pb1[12], pb2[6];
    float cS;      // bq . bk
};

__constant__ ConstW cw;

namespace {

constexpr int N = 8;
constexpr int D = 12;
constexpr int F = 24;
constexpr int V = 128;
constexpr int WARPS = 8;
constexpr int THREADS = WARPS * 32;
constexpr int ITEMS_PER_BLOCK = 32;   // 4 items per warp
constexpr int XROW = 16;              // X row stride (12 data + d at [12])
constexpr int ISTX = 132;             // X item stride (bank stagger +4/group)
constexpr int XV   = 4 * ISTX;        // V' region offset (528)
constexpr int ISTV = 100;             // V' item stride (bank stagger +4/group)
constexpr int SCR  = XV + 4 * ISTV;   // 928 floats per warp

#define F4C(p) (*reinterpret_cast<const float4*>(p))
#define F4(p)  (*reinterpret_cast<float4*>(p))

__device__ __forceinline__ ull pack2(float x, float y) {
    ull p; asm("mov.b64 %0, {%1, %2};" : "=l"(p) : "f"(x), "f"(y)); return p;
}
__device__ __forceinline__ void unpack2(ull p, float& x, float& y) {
    asm("mov.b64 {%0, %1}, %2;" : "=f"(x), "=f"(y) : "l"(p));
}
__device__ __forceinline__ void ffma2(ull& d, ull a, ull b) {
    asm("fma.rn.f32x2 %0, %1, %2, %0;" : "+l"(d) : "l"(a), "l"(b));
}

// ---- pack kernel: trigger PDL immediately, stage weights to smem
//      (coalesced), fold from smem, write into the constant bank ----
__global__ void pack_weights_kernel(
    ConstW* __restrict__ dst,
    const float* __restrict__ Wq, const float* __restrict__ bq,
    const float* __restrict__ Wk, const float* __restrict__ bk,
    const float* __restrict__ Wv, const float* __restrict__ bv,
    const float* __restrict__ Wo, const float* __restrict__ bo,
    const float* __restrict__ W1, const float* __restrict__ b1,
    const float* __restrict__ W2, const float* __restrict__ b2)
{
    // let the dependent main kernel start launching right away
    cudaTriggerProgrammaticLaunchCompletion();

    __shared__ float sWq[144], sWk[144], sWv[144], sWo[144];
    __shared__ float sW1[288], sW2[288];
    __shared__ float sbq[12], sbk[12], sbv[12], sbo[12], sb2[12], sb1[24];

    const int t = threadIdx.x;

    // coalesced parallel staging (independent loads, latency overlapped)
    if (t < 144) { sWq[t] = Wq[t]; sWk[t] = Wk[t]; sWv[t] = Wv[t]; sWo[t] = Wo[t]; }
    {
        int u = t - 144;
        if (u >= 0 && u < 112) {           // 144..255 covers first 112 of W1/W2
            sW1[u] = W1[u]; sW2[u] = W2[u];
        }
    }
    if (t < 176) { sW1[112 + t] = W1[112 + t]; sW2[112 + t] = W2[112 + t]; }
    if (t < 12) {
        sbq[t] = bq[t]; sbk[t] = bk[t]; sbv[t] = bv[t];
        sbo[t] = bo[t]; sb2[t] = b2[t];
    }
    if (t < 24) sb1[t] = b1[t];
    __syncthreads();

    // G = Wq^T Wk : pG[e*6+p] = (G[e][2p], G[e][2p+1])
    if (t < 72) {
        int e = t / 6, p = t % 6;
        float g0 = 0.f, g1 = 0.f;
        #pragma unroll
        for (int d = 0; d < D; d++) {
            g0 += sWq[d * D + e] * sWk[d * D + 2*p];
            g1 += sWq[d * D + e] * sWk[d * D + 2*p + 1];
        }
        dst->pG[t] = pack2(g0, g1);
    }
    // Wvo = Wo @ Wv : pWvo[e*6+p] = (Wvo[2p][e], Wvo[2p+1][e])
    if (t >= 72 && t < 144) {
        int i = t - 72;
        int e = i / 6, p = i % 6;
        float w0 = 0.f, w1 = 0.f;
        #pragma unroll
        for (int d = 0; d < D; d++) {
            w0 += sWo[(2*p)     * D + d] * sWv[d * D + e];
            w1 += sWo[(2*p + 1) * D + d] * sWv[d * D + e];
        }
        dst->pWvo[i] = pack2(w0, w1);
    }
    for (int i = t; i < 144; i += 256) {
        int e = i / 12, p = i % 12;
        dst->pW1[i] = pack2(sW1[(2*p) * D + e], sW1[(2*p+1) * D + e]);
    }
    for (int i = t; i < 144; i += 256) {
        int f = i / 6, p = i % 6;
        dst->pW2[i] = pack2(sW2[(2*p) * F + f], sW2[(2*p+1) * F + f]);
    }
    if (t >= 144 && t < 150) {
        int q = t - 144;
        float a0 = 0.f, a1 = 0.f, b0 = 0.f, b1v = 0.f, v0 = 0.f, v1 = 0.f;
        #pragma unroll
        for (int d = 0; d < D; d++) {
            a0  += sWq[d * D + 2*q]     * sbk[d];
            a1  += sWq[d * D + 2*q + 1] * sbk[d];
            b0  += sbq[d] * sWk[d * D + 2*q];
            b1v += sbq[d] * sWk[d * D + 2*q + 1];
            v0  += sWo[(2*q)     * D + d] * sbv[d];
            v1  += sWo[(2*q + 1) * D + d] * sbv[d];
        }
        dst->pa[q]   = pack2(a0, a1);
        dst->pbd[q]  = pack2(b0, b1v);
        dst->pbvo[q] = pack2(v0, v1);
        dst->pbo[q]  = pack2(sbo[2*q], sbo[2*q+1]);
        dst->pb2[q]  = pack2(sb2[2*q], sb2[2*q+1]);
    }
    if (t >= 150 && t < 162) {
        int q = t - 150;
        dst->pb1[q] = pack2(sb1[2*q], sb1[2*q+1]);
    }
    if (t == 162) {
        float c = 0.f;
        #pragma unroll
        for (int d = 0; d < D; d++) c += sbq[d] * sbk[d];
        dst->cS = c;
    }
}

__global__ __launch_bounds__(THREADS, 3)
void tiny_transformer_kernel(
    const int*   __restrict__ x,
    const float* __restrict__ embed,
    const float* __restrict__ pos,
    const float* __restrict__ blm,
    float* __restrict__ out)
{
    // ---- shared ----
    __shared__ __align__(16) float sEmbT[D * V];   // transposed [d][v] for logits
    __shared__ __align__(16) float sPos[N * D];
    __shared__ __align__(16) float sBlm[V];
    // per-warp scratch: X rows (+d) at [0..528), V' rows at [528..928);
    // low 384 floats reused for final X in phase 9.
    __shared__ __align__(16) float sScr[WARPS][SCR];

    const int tid = threadIdx.x;

    // staging (independent of the pack kernel's output)
    for (int i = tid; i < D * V; i += THREADS) {
        int d = i >> 7, v = i & 127;
        sEmbT[i] = embed[v * D + d];
    }
    for (int i = tid; i < N * D; i += THREADS) sPos[i] = pos[i];
    for (int i = tid; i < V; i += THREADS) sBlm[i] = blm[i];
    __syncthreads();

    // wait for the pack kernel's constant-bank writes (PDL dependency;
    // no-op under a plain serialized launch)
    cudaGridDependencySynchronize();

    const int w    = tid >> 5;
    const int lane = tid & 31;
    const int n    = lane & 7;            // token within item
    const int g    = lane >> 3;           // item within warp
    const int item_base = blockIdx.x * ITEMS_PER_BLOCK + w * 4;

    // ---- phase 1: X = embed[x] + pos ----
    const int tok = __ldg(&x[item_base * N + lane]);
    float X[D];
    {
        const float4* e4 = reinterpret_cast<const float4*>(embed);
        #pragma unroll
        for (int c = 0; c < 3; c++) {
            float4 e = __ldg(&e4[tok * 3 + c]);
            float4 p = F4C(&sPos[n * D + 4 * c]);
            X[4*c+0] = e.x + p.x; X[4*c+1] = e.y + p.y;
            X[4*c+2] = e.z + p.z; X[4*c+3] = e.w + p.w;
        }
    }

    // ---- phase 2: Y = X@G, V' = X@Wvo^T + bvo, bias dots; X,V' -> smem ----
    ull y2[6];
    float cOwn;
    {
        ull v2[6];
        #pragma unroll
        for (int p = 0; p < 6; p++) { y2[p] = 0; v2[p] = cw.pbvo[p]; }
        #pragma unroll
        for (int e = 0; e < D; e++) {
            const ull xp = pack2(X[e], X[e]);
            #pragma unroll
            for (int p = 0; p < 6; p++) {
                ffma2(y2[p], xp, cw.pG[e * 6 + p]);
                ffma2(v2[p], xp, cw.pWvo[e * 6 + p]);
            }
        }
        // bias dots: cOwn = X.a ; dOwn = X.b
        ull cacc = 0, dacc = 0;
        #pragma unroll
        for (int p = 0; p < 6; p++) {
            const ull xq = pack2(X[2*p], X[2*p+1]);
            ffma2(cacc, xq, cw.pa[p]);
            ffma2(dacc, xq, cw.pbd[p]);
        }
        float cu, cv, du, dv;
        unpack2(cacc, cu, cv); cOwn = cu + cv;
        unpack2(dacc, du, dv); const float dOwn = du + dv;

        // store X row (+d) for score phase
        float* xr = &sScr[w][g * ISTX + n * XROW];
        F4(xr)     = make_float4(X[0], X[1], X[2],  X[3]);
        F4(xr + 4) = make_float4(X[4], X[5], X[6],  X[7]);
        F4(xr + 8) = make_float4(X[8], X[9], X[10], X[11]);
        xr[12] = dOwn;
        // store V' row packed-natural
        ulonglong2* vd =
            reinterpret_cast<ulonglong2*>(&sScr[w][XV + g * ISTV + n * D]);
        vd[0] = make_ulonglong2(v2[0], v2[1]);
        vd[1] = make_ulonglong2(v2[2], v2[3]);
        vd[2] = make_ulonglong2(v2[4], v2[5]);
    }
    __syncwarp();

    // ---- phase 3: S[n][m] = (Y_n.X_m + c_n + d_m + cS)/sqrt(D) ----
    float S[N];
    {
        const float inv_scale = 0.28867513459481287f;  // 1/sqrt(12)
        const float* xb = &sScr[w][g * ISTX];
        const float base = cOwn + cw.cS;
        #pragma unroll
        for (int m = 0; m < N; m++) {
            const ulonglong2* xm =
                reinterpret_cast<const ulonglong2*>(xb + m * XROW);
            ulonglong2 r0 = xm[0], r1 = xm[1], r2 = xm[2];
            ull acc = 0;
            ffma2(acc, y2[0], r0.x); ffma2(acc, y2[1], r0.y);
            ffma2(acc, y2[2], r1.x); ffma2(acc, y2[3], r1.y);
            ffma2(acc, y2[4], r2.x); ffma2(acc, y2[5], r2.y);
            float u, v; unpack2(acc, u, v);
            const float dm = xb[m * XROW + 12];
            S[m] = (m <= n) ? (u + v + base + dm) * inv_scale : -1e30f;
        }
    }

    // ---- phase 4: softmax ----
    {
        float mx = S[0];
        #pragma unroll
        for (int m = 1; m < N; m++) mx = fmaxf(mx, S[m]);
        float sum = 0.f;
        #pragma unroll
        for (int m = 0; m < N; m++) { S[m] = __expf(S[m] - mx); sum += S[m]; }
        const float inv = 1.f / sum;
        #pragma unroll
        for (int m = 0; m < N; m++) S[m] *= inv;
    }

    // ---- phase 5+6: X += softmax @ V' + bo  (VO-folded attention out) ----
    {
        ull a2[6] = {0, 0, 0, 0, 0, 0};
        const ulonglong2* vb =
            reinterpret_cast<const ulonglong2*>(&sScr[w][XV + g * ISTV]);
        #pragma unroll
        for (int m = 0; m < N; m++) {
            const ull sp = pack2(S[m], S[m]);
            ulonglong2 r0 = vb[m * 3], r1 = vb[m * 3 + 1], r2 = vb[m * 3 + 2];
            ffma2(a2[0], sp, r0.x); ffma2(a2[1], sp, r0.y);
            ffma2(a2[2], sp, r1.x); ffma2(a2[3], sp, r1.y);
            ffma2(a2[4], sp, r2.x); ffma2(a2[5], sp, r2.y);
        }
        #pragma unroll
        for (int p = 0; p < 6; p++) {
            float u, v, bu, bv_;
            unpack2(a2[p], u, v);
            unpack2(cw.pbo[p], bu, bv_);
            X[2*p]   += u + bu;
            X[2*p+1] += v + bv_;
        }
    }

    // ---- phase 7: H = relu(X @ W1^T + b1) (packed) ----
    float H[F];
    {
        ull h2[12];
        #pragma unroll
        for (int p = 0; p < 12; p++) h2[p] = cw.pb1[p];
        #pragma unroll
        for (int e = 0; e < D; e++) {
            const ull xp = pack2(X[e], X[e]);
            #pragma unroll
            for (int p = 0; p < 12; p++)
                ffma2(h2[p], xp, cw.pW1[e * 12 + p]);
        }
        #pragma unroll
        for (int p = 0; p < 12; p++) {
            float u, v; unpack2(h2[p], u, v);
            H[2*p]   = fmaxf(u, 0.f);
            H[2*p+1] = fmaxf(v, 0.f);
        }
    }

    // ---- phase 8: X += H @ W2^T + b2 (packed) ----
    {
        ull x2[6];
        #pragma unroll
        for (int p = 0; p < 6; p++) x2[p] = cw.pb2[p];
        #pragma unroll
        for (int f = 0; f < F; f++) {
            const ull hp = pack2(H[f], H[f]);
            #pragma unroll
            for (int p = 0; p < 6; p++)
                ffma2(x2[p], hp, cw.pW2[f * 6 + p]);
        }
        #pragma unroll
        for (int p = 0; p < 6; p++) {
            float u, v; unpack2(x2[p], u, v);
            X[2*p] += u; X[2*p+1] += v;
        }
    }

    // ---- hand off final X (reuses scratch; all reads done) ----
    __syncwarp();
    {
        float* dst = &sScr[w][lane * D];
        F4(dst)     = make_float4(X[0], X[1], X[2],  X[3]);
        F4(dst + 4) = make_float4(X[4], X[5], X[6],  X[7]);
        F4(dst + 8) = make_float4(X[8], X[9], X[10], X[11]);
    }
    __syncwarp();

    // ---- phase 9: logits = Xf @ embed^T + b_lm (single pass, 4 cols/lane) ----
    {
        const int v0 = lane * 4;
        ull e01[D], e23[D];
        #pragma unroll
        for (int d = 0; d < D; d++) {
            float4 e = F4C(&sEmbT[d * V + v0]);
            e01[d] = pack2(e.x, e.y);
            e23[d] = pack2(e.z, e.w);
        }
        const float4 bl = F4C(&sBlm[v0]);
        const ull bl01 = pack2(bl.x, bl.y);
        const ull bl23 = pack2(bl.z, bl.w);

        float* obase = out + (size_t)item_base * (N * V) + v0;
        const float* xf = sScr[w];

        for (int r = 0; r < 4 * N; r++) {
            float4 xa = F4C(&xf[r * D]);       // broadcast reads
            float4 xb = F4C(&xf[r * D + 4]);
            float4 xc = F4C(&xf[r * D + 8]);
            const float xr[D] = {xa.x, xa.y, xa.z, xa.w,
                                 xb.x, xb.y, xb.z, xb.w,
                                 xc.x, xc.y, xc.z, xc.w};
            ull a01 = bl01, a23 = bl23;
            #pragma unroll
            for (int d = 0; d < D; d++) {
                const ull xv2 = pack2(xr[d], xr[d]);
                ffma2(a01, xv2, e01[d]);
                ffma2(a23, xv2, e23[d]);
            }
            float4 acc;
            unpack2(a01, acc.x, acc.y);
            unpack2(a23, acc.z, acc.w);
            F4(&obase[(size_t)r * V]) = acc;   // coalesced 512B per warp-row
        }
    }
}

}  // namespace

extern "C" void kernel_launch(void* const* d_in, const int* in_sizes, int n_in,
                              void* d_out, int out_size)
{
    const int*   x     = (const int*)  d_in[0];
    const float* embed = (const float*)d_in[1];
    const float* pos   = (const float*)d_in[2];
    const float* blm   = (const float*)d_in[15];
    float* out = (float*)d_out;

    // symbol address query (host-side, not a captured op)
    void* cwAddr = nullptr;
    cudaGetSymbolAddress(&cwAddr, cw);

    // 1) fold + pair-pack all weights DIRECTLY into the constant bank;
    //    triggers programmatic launch completion immediately.
    pack_weights_kernel<<<1, 256>>>(
        (ConstW*)cwAddr,
        (const float*)d_in[3],  (const float*)d_in[4],
        (const float*)d_in[5],  (const float*)d_in[6],
        (const float*)d_in[7],  (const float*)d_in[8],
        (const float*)d_in[9],  (const float*)d_in[10],
        (const float*)d_in[11], (const float*)d_in[12],
        (const float*)d_in[13], (const float*)d_in[14]);

    // 2) main kernel with PDL: launches/stages while pack still runs,
    //    grid-syncs before first constant read.
    const int batch  = in_sizes[0] / N;              // 32768
    const int blocks = batch / ITEMS_PER_BLOCK;      // 1024

    cudaLaunchConfig_t cfg = {};
    cfg.gridDim  = dim3(blocks, 1, 1);
    cfg.blockDim = dim3(THREADS, 1, 1);
    cudaLaunchAttribute attrs[1];
    attrs[0].id = cudaLaunchAttributeProgrammaticStreamSerialization;
    attrs[0].val.programmaticStreamSerializationAllowed = 1;
    cfg.attrs = attrs;
    cfg.numAttrs = 1;

    cudaError_t err = cudaLaunchKernelEx(&cfg, tiny_transformer_kernel,
                                         x, embed, pos, blm, out);
    if (err != cudaSuccess) {
        // fallback: plain serialized launch (grid-sync is then a no-op)
        tiny_transformer_kernel<<<blocks, THREADS>>>(x, embed, pos, blm, out);
    }
}